// round 5
// baseline (speedup 1.0000x reference)
#include <cuda_runtime.h>
#include <math.h>

typedef unsigned long long ull;

#define T_STEPS 512
#define NHID    512
#define NCH     1024
#define BATCH   64
#define HB      32768
#define NCTA    128
#define NTHR    256
#define RPAD    513
#define SDUP_ULL (2*16*RPAD)
#define RED_ULL  (16*8*2*9)
#define SMEM_BYTES ((SDUP_ULL + RED_ULL) * 8)

__device__ float g_X[(size_t)T_STEPS * BATCH * NCH];  // x @ W0[:512], [T*B][1024]
__device__ float g_S[9][HB];
__device__ unsigned int g_bar_arrive;
__device__ unsigned int g_bar_gen;

__device__ __forceinline__ void fma2(ull &d, ull a, ull b) {
    asm("fma.rn.f32x2 %0, %1, %2, %0;" : "+l"(d) : "l"(a), "l"(b));
}
__device__ __forceinline__ ull dup2(float v) {
    ull r; asm("mov.b64 %0, {%1, %1};" : "=l"(r) : "f"(v)); return r;
}
__device__ __forceinline__ float2 unpk(ull v) {
    float2 f; asm("mov.b64 {%0, %1}, %2;" : "=f"(f.x), "=f"(f.y) : "l"(v)); return f;
}

__device__ __forceinline__ void grid_bar() {
    __syncthreads();
    if (threadIdx.x == 0) {
        unsigned int gen = ((volatile unsigned int*)&g_bar_gen)[0];
        __threadfence();
        if (atomicAdd(&g_bar_arrive, 1u) == (unsigned)(NCTA - 1)) {
            g_bar_arrive = 0u;
            __threadfence();
            ((volatile unsigned int*)&g_bar_gen)[0] = gen + 1u;
        } else {
            while (((volatile unsigned int*)&g_bar_gen)[0] == gen) { }
        }
        __threadfence();
    }
    __syncthreads();
}

__device__ __forceinline__ float actf(int a, float x) {
    if (a == 0) return tanhf(x);
    if (a == 1) return fmaxf(x, 0.f);
    if (a == 2) return 1.f / (1.f + expf(-x));
    return x;
}

// ---------------- X = inputs @ W0[:512] precompute ----------------
__global__ void __launch_bounds__(256) xprep_kernel(const float* __restrict__ A,
                                                    const float* __restrict__ W) {
    __shared__ ull   AsD[64][17];
    __shared__ float Bs[16][68];
    const int tid = threadIdx.x;
    const int n0 = blockIdx.x * 64;
    const int m0 = blockIdx.y * 64;
    const int tx = tid & 15;
    const int ty = tid >> 4;
    ull acc[4][2];
#pragma unroll
    for (int i = 0; i < 4; ++i) { acc[i][0] = 0ull; acc[i][1] = 0ull; }
    for (int k0 = 0; k0 < 512; k0 += 16) {
        {
            int am = tid >> 2, a4 = tid & 3;
            float4 v = *(const float4*)(A + (size_t)(m0 + am) * 512 + k0 + a4 * 4);
            AsD[am][a4 * 4 + 0] = dup2(v.x); AsD[am][a4 * 4 + 1] = dup2(v.y);
            AsD[am][a4 * 4 + 2] = dup2(v.z); AsD[am][a4 * 4 + 3] = dup2(v.w);
        }
        {
            int bk = tid >> 4, b4 = tid & 15;
            *(float4*)&Bs[bk][b4 * 4] = *(const float4*)(W + (size_t)(k0 + bk) * NCH + n0 + b4 * 4);
        }
        __syncthreads();
#pragma unroll
        for (int k = 0; k < 16; ++k) {
            ulonglong2 b = *(const ulonglong2*)&Bs[k][tx * 4];
#pragma unroll
            for (int i = 0; i < 4; ++i) {
                ull a = AsD[ty * 4 + i][k];
                fma2(acc[i][0], a, b.x);
                fma2(acc[i][1], a, b.y);
            }
        }
        __syncthreads();
    }
#pragma unroll
    for (int i = 0; i < 4; ++i) {
        float2 lo = unpk(acc[i][0]), hi = unpk(acc[i][1]);
        *(float4*)(g_X + (size_t)(m0 + ty * 4 + i) * NCH + n0 + tx * 4) =
            make_float4(lo.x, lo.y, hi.x, hi.y);
    }
}

// ---------------- fused phase: NG gemms sharing NP staged predecessors ----------------
template<int NG, int NP, bool MEAN, bool BIAS>
__device__ __forceinline__ void phase(
    ull* sdup, ull* redbuf,
    const float* p0, const float* p1,
    const float* w0_, const float* w1_, const float* w2_, const float* w3_,
    int a0, int a1, int a2, int a3,
    float* d0, float* d1, float* d2, float* d3,
    const float* bias, float* outp, int r0, int j0)
{
    const int tid = threadIdx.x;
    const int jp = tid & 7;
    const int rg = (tid >> 3) & 3;
    const int kq = tid >> 5;
    const float* preds[2] = {p0, p1};
    const float* W[4]     = {w0_, w1_, w2_, w3_};
    const int    acts[4]  = {a0, a1, a2, a3};
    float*       dsts[4]  = {d0, d1, d2, d3};

    // stage predecessor rows into smem, duplicated as f32x2 pairs
    for (int i = tid; i < NP * 2048; i += NTHR) {
        int p = i >> 11;
        int rem = i & 2047;
        int r = rem >> 7;
        int k4 = (rem & 127) << 2;
        float4 v = *(const float4*)(preds[p] + (size_t)(r0 + r) * NHID + k4);
        ull* d = sdup + p * 16 * RPAD + r * RPAD + k4;
        d[0] = dup2(v.x); d[1] = dup2(v.y); d[2] = dup2(v.z); d[3] = dup2(v.w);
    }
    __syncthreads();

    ull acc[NG][4][2];
#pragma unroll
    for (int g = 0; g < NG; ++g)
#pragma unroll
        for (int rr = 0; rr < 4; ++rr) { acc[g][rr][0] = 0ull; acc[g][rr][1] = 0ull; }

    const int kbase = kq * 64;
    const ull* srow0 = sdup + (rg * 4) * RPAD + kbase;
    const ull* srow1 = sdup + 16 * RPAD + (rg * 4) * RPAD + kbase;
    const float* wb[4];
#pragma unroll
    for (int g = 0; g < NG; ++g)
        wb[g] = W[g] + (size_t)kbase * NCH + j0 + jp * 2;

#pragma unroll 4
    for (int kk = 0; kk < 64; ++kk) {
        ull sv[NP][4];
#pragma unroll
        for (int rr = 0; rr < 4; ++rr) sv[0][rr] = srow0[rr * RPAD + kk];
        if (NP == 2) {
#pragma unroll
            for (int rr = 0; rr < 4; ++rr) sv[1][rr] = srow1[rr * RPAD + kk];
        }
#pragma unroll
        for (int g = 0; g < NG; ++g) {
            const float* wp = wb[g] + kk * NCH;
            ull wc = *(const ull*)(wp);
            ull wh = *(const ull*)(wp + NHID);
            const int p = (NP == 1) ? 0 : ((NG == 4) ? (g >> 1) : g);
#pragma unroll
            for (int rr = 0; rr < 4; ++rr) {
                fma2(acc[g][rr][0], sv[p][rr], wc);
                fma2(acc[g][rr][1], sv[p][rr], wh);
            }
        }
    }

    float m0v = 0.f, m1v = 0.f;
#pragma unroll
    for (int g = 0; g < NG; ++g) {
        __syncthreads();
#pragma unroll
        for (int rr = 0; rr < 4; ++rr) {
            int rloc = rg * 4 + rr;
            redbuf[(((rloc * 8 + jp) * 2) + 0) * 9 + kq] = acc[g][rr][0];
            redbuf[(((rloc * 8 + jp) * 2) + 1) * 9 + kq] = acc[g][rr][1];
        }
        __syncthreads();
        if (tid < 128) {
            int r = tid >> 3, jpp = tid & 7;
            float cx = 0.f, cy = 0.f, hx = 0.f, hy = 0.f;
#pragma unroll
            for (int q = 0; q < 8; ++q) {
                float2 a = unpk(redbuf[((r * 8 + jpp) * 2 + 0) * 9 + q]);
                float2 b = unpk(redbuf[((r * 8 + jpp) * 2 + 1) * 9 + q]);
                cx += a.x; cy += a.y; hx += b.x; hy += b.y;
            }
            int jc = j0 + jpp * 2;
            if (BIAS) {
                float2 bc = *(const float2*)(bias + (size_t)(r0 + r) * NCH + jc);
                float2 bh = *(const float2*)(bias + (size_t)(r0 + r) * NCH + NHID + jc);
                cx += bc.x; cy += bc.y; hx += bh.x; hy += bh.y;
            }
            const int p = (NP == 1) ? 0 : ((NG == 4) ? (g >> 1) : g);
            float sp0 = unpk(sdup[p * 16 * RPAD + r * RPAD + jc]).x;
            float sp1 = unpk(sdup[p * 16 * RPAD + r * RPAD + jc + 1]).x;
            float cg0 = 1.f / (1.f + expf(-cx));
            float cg1 = 1.f / (1.f + expf(-cy));
            float hv0 = actf(acts[g], hx);
            float hv1 = actf(acts[g], hy);
            float n0 = sp0 + cg0 * (hv0 - sp0);
            float n1 = sp1 + cg1 * (hv1 - sp1);
            if (dsts[g] != nullptr)
                *(float2*)(dsts[g] + (size_t)(r0 + r) * NHID + jc) = make_float2(n0, n1);
            if (MEAN) { m0v += n0; m1v += n1; }
        }
    }
    if (MEAN) {
        if (tid < 128) {
            int r = tid >> 3, jc = j0 + (tid & 7) * 2;
#pragma unroll
            for (int st = 1; st <= 6; ++st) {
                float2 v = *(const float2*)(g_S[st] + (size_t)(r0 + r) * NHID + jc);
                m0v += v.x; m1v += v.y;
            }
            *(float2*)(outp + (size_t)(r0 + r) * NHID + jc) =
                make_float2(m0v * 0.125f, m1v * 0.125f);
        }
    }
}

__global__ void __launch_bounds__(NTHR, 1) recurrent_kernel(
    const float* __restrict__ hidden0, const float* __restrict__ W0,
    const float* __restrict__ Ws, float* __restrict__ out, int write_tail)
{
    extern __shared__ ull smem[];
    ull* sdup = smem;
    ull* redbuf = smem + SDUP_ULL;
    const int bid = blockIdx.x;
    const int r0 = (bid >> 5) * 16;
    const int j0 = (bid & 31) * 16;
    const float* W0h = W0 + (size_t)NHID * NCH;
    const size_t WS = (size_t)NHID * NCH;

    for (int t = 0; t < T_STEPS; ++t) {
        const float* hprev = (t == 0) ? hidden0 : (out + (size_t)(t - 1) * HB);
        // P0: s0 = gate(hprev@W0h + X[t]); h-act = tanh
        phase<1, 1, false, true>(sdup, redbuf, hprev, nullptr,
            W0h, nullptr, nullptr, nullptr, 0, 0, 0, 0,
            g_S[0], nullptr, nullptr, nullptr,
            g_X + (size_t)t * BATCH * NCH, nullptr, r0, j0);
        grid_bar();
        // P1: s1 = tanh-gemm(s0), s2 = relu-gemm(s0)
        phase<2, 1, false, false>(sdup, redbuf, g_S[0], nullptr,
            Ws + 0 * WS, Ws + 1 * WS, nullptr, nullptr, 0, 1, 0, 0,
            g_S[1], g_S[2], nullptr, nullptr, nullptr, nullptr, r0, j0);
        grid_bar();
        // P2: s3=sig(s1), s4=id(s1), s5=tanh(s2), s6=relu(s2)
        phase<4, 2, false, false>(sdup, redbuf, g_S[1], g_S[2],
            Ws + 2 * WS, Ws + 3 * WS, Ws + 4 * WS, Ws + 5 * WS, 2, 3, 0, 1,
            g_S[3], g_S[4], g_S[5], g_S[6], nullptr, nullptr, r0, j0);
        grid_bar();
        // P3: s7=sig(s3), s8=id(s4); fused mean of s1..s8 -> out[t]
        phase<2, 2, true, false>(sdup, redbuf, g_S[3], g_S[4],
            Ws + 6 * WS, Ws + 7 * WS, nullptr, nullptr, 2, 3, 0, 0,
            nullptr, nullptr, nullptr, nullptr,
            nullptr, out + (size_t)t * HB, r0, j0);
        grid_bar();
    }
    if (write_tail) {
        const float* src = out + (size_t)(T_STEPS - 1) * HB;
        float* dstp = out + (size_t)T_STEPS * HB;
        for (int i = bid * NTHR + threadIdx.x; i < HB; i += NCTA * NTHR)
            dstp[i] = src[i];
    }
}

extern "C" void kernel_launch(void* const* d_in, const int* in_sizes, int n_in,
                              void* d_out, int out_size) {
    const float* inputs = (const float*)d_in[0];   // [512,64,512]
    const float* hidden = (const float*)d_in[1];   // [1,64,512]
    const float* W0     = (const float*)d_in[2];   // [1024,1024]
    const float* Ws     = (const float*)d_in[3];   // [8,512,1024]
    float* out = (float*)d_out;

    dim3 gx(NCH / 64, (T_STEPS * BATCH) / 64);
    xprep_kernel<<<gx, 256>>>(inputs, W0);

    cudaFuncSetAttribute(recurrent_kernel,
                         cudaFuncAttributeMaxDynamicSharedMemorySize, SMEM_BYTES);
    int tail = (out_size >= T_STEPS * HB + HB) ? 1 : 0;
    recurrent_kernel<<<NCTA, NTHR, SMEM_BYTES>>>(hidden, W0, Ws, out, tail);
}

// round 6
// speedup vs baseline: 1.0976x; 1.0976x over previous
#include <cuda_runtime.h>
#include <math.h>
#include <stdint.h>

typedef unsigned long long ull;

#define T_STEPS 512
#define NHID    512
#define NCH     1024
#define BATCH   64
#define HB      32768
#define NCTA    128
#define NTHR    512
#define NCHUNK  8
// dynamic smem layout (bytes)
#define WS_OFF       65536                    // states: 2 preds * 16 rows * 512 f32
#define WS_BUF_BYTES 36864                    // 256 rows * 144B (max NG=4)
#define RED_OFF      (WS_OFF + 2*WS_BUF_BYTES)
#define SMEM_BYTES   (RED_OFF + 2048*8)       // 155648

__device__ float g_X[(size_t)T_STEPS * BATCH * NCH];   // x @ W0[:512]
__device__ float g_S[9][HB];
__device__ ull   g_WT2[(size_t)9 * 256 * 1024];        // [g][kpair][j] = (w[2p][j], w[2p+1][j])
__device__ unsigned int g_bar_arrive;
__device__ unsigned int g_bar_gen;

__device__ __forceinline__ void fma2(ull &d, ull a, ull b) {
    asm("fma.rn.f32x2 %0, %1, %2, %0;" : "+l"(d) : "l"(a), "l"(b));
}
__device__ __forceinline__ ull dup2(float v) {
    ull r; asm("mov.b64 %0, {%1, %1};" : "=l"(r) : "f"(v)); return r;
}
__device__ __forceinline__ float2 unpk(ull v) {
    float2 f; asm("mov.b64 {%0, %1}, %2;" : "=f"(f.x), "=f"(f.y) : "l"(v)); return f;
}
__device__ __forceinline__ uint32_t smem_u32(const void* p) {
    uint32_t a;
    asm("{ .reg .u64 t; cvta.to.shared.u64 t, %1; cvt.u32.u64 %0, t; }" : "=r"(a) : "l"(p));
    return a;
}
__device__ __forceinline__ void cp16(uint32_t d, const void* s) {
    asm volatile("cp.async.cg.shared.global [%0], [%1], 16;" :: "r"(d), "l"(s) : "memory");
}

__device__ __forceinline__ void grid_bar() {
    __syncthreads();
    if (threadIdx.x == 0) {
        unsigned int gen = ((volatile unsigned int*)&g_bar_gen)[0];
        __threadfence();
        if (atomicAdd(&g_bar_arrive, 1u) == (unsigned)(NCTA - 1)) {
            g_bar_arrive = 0u;
            __threadfence();
            ((volatile unsigned int*)&g_bar_gen)[0] = gen + 1u;
        } else {
            while (((volatile unsigned int*)&g_bar_gen)[0] == gen) { }
        }
        __threadfence();
    }
    __syncthreads();
}

__device__ __forceinline__ float actf(int a, float x) {
    if (a == 0) return tanhf(x);
    if (a == 1) return fmaxf(x, 0.f);
    if (a == 2) return 1.f / (1.f + expf(-x));
    return x;
}

// ------- one-time weight transpose into k-pair-interleaved layout -------
__global__ void wtrans_kernel(const float* __restrict__ W0, const float* __restrict__ Ws) {
    int g = blockIdx.x;   // 0..8; 8 = W0 hidden half
    int p = blockIdx.y;   // 0..255 k-pairs
    const float* src = (g == 8) ? (W0 + (size_t)NHID * NCH) : (Ws + (size_t)g * NHID * NCH);
    const float* ra = src + (size_t)(2 * p) * NCH;
    const float* rb = ra + NCH;
    for (int j = threadIdx.x; j < NCH; j += 256) {
        ull v; asm("mov.b64 %0, {%1, %2};" : "=l"(v) : "f"(ra[j]), "f"(rb[j]));
        g_WT2[((size_t)g * 256 + p) * 1024 + j] = v;
    }
}

// ------- X = inputs @ W0[:512] precompute -------
__global__ void __launch_bounds__(256) xprep_kernel(const float* __restrict__ A,
                                                    const float* __restrict__ W) {
    __shared__ ull   AsD[64][17];
    __shared__ float Bs[16][68];
    const int tid = threadIdx.x;
    const int n0 = blockIdx.x * 64;
    const int m0 = blockIdx.y * 64;
    const int tx = tid & 15;
    const int ty = tid >> 4;
    ull acc[4][2];
#pragma unroll
    for (int i = 0; i < 4; ++i) { acc[i][0] = 0ull; acc[i][1] = 0ull; }
    for (int k0 = 0; k0 < 512; k0 += 16) {
        {
            int am = tid >> 2, a4 = tid & 3;
            float4 v = *(const float4*)(A + (size_t)(m0 + am) * 512 + k0 + a4 * 4);
            AsD[am][a4 * 4 + 0] = dup2(v.x); AsD[am][a4 * 4 + 1] = dup2(v.y);
            AsD[am][a4 * 4 + 2] = dup2(v.z); AsD[am][a4 * 4 + 3] = dup2(v.w);
        }
        {
            int bk = tid >> 4, b4 = tid & 15;
            *(float4*)&Bs[bk][b4 * 4] = *(const float4*)(W + (size_t)(k0 + bk) * NCH + n0 + b4 * 4);
        }
        __syncthreads();
#pragma unroll
        for (int k = 0; k < 16; ++k) {
            ulonglong2 b = *(const ulonglong2*)&Bs[k][tx * 4];
#pragma unroll
            for (int i = 0; i < 4; ++i) {
                ull a = AsD[ty * 4 + i][k];
                fma2(acc[i][0], a, b.x);
                fma2(acc[i][1], a, b.y);
            }
        }
        __syncthreads();
    }
#pragma unroll
    for (int i = 0; i < 4; ++i) {
        float2 lo = unpk(acc[i][0]), hi = unpk(acc[i][1]);
        *(float4*)(g_X + (size_t)(m0 + ty * 4 + i) * NCH + n0 + tx * 4) =
            make_float4(lo.x, lo.y, hi.x, hi.y);
    }
}

// ------- fused phase: NG gemms, NP staged predecessors, cp.async weight pipeline -------
template<int NG, int NP, bool MEAN, bool BIAS>
__device__ __forceinline__ void phase(char* smem, uint32_t ws_u32,
    const float* p0, const float* p1,
    int gi0, int gi1, int gi2, int gi3,
    int a0, int a1, int a2, int a3,
    float* d0, float* d1, float* d2, float* d3,
    const float* bias, float* outp, int r0, int j0)
{
    float* sA = (float*)smem;
    ull*   red = (ull*)(smem + RED_OFF);
    const int tid = threadIdx.x;
    const int jj = tid & 15;            // j column within tile
    const int rh = (tid >> 4) & 7;      // 2-row group
    const int kq = tid >> 7;            // K split (4 ways, 128 k each)

    // stage predecessor states (non-duplicated f32)
    {
        const float* preds[2] = { p0, p1 };
#pragma unroll
        for (int p = 0; p < NP; ++p) {
#pragma unroll
            for (int i = tid; i < 2048; i += NTHR) {
                int r = i >> 7, k4 = (i & 127) << 2;
                *(float4*)(sA + p * 8192 + r * 512 + k4) =
                    *(const float4*)(preds[p] + (size_t)(r0 + r) * NHID + k4);
            }
        }
    }

    const int seg = tid & 7, ko2 = (tid >> 3) & 7, chn = (tid >> 6) & 1, kqv = tid >> 7;
    auto issue = [&](int c) {
        uint32_t dbase = ws_u32 + (c & 1) * WS_BUF_BYTES;
#pragma unroll
        for (int g = 0; g < NG; ++g) {
            int gi = (g == 0) ? gi0 : (g == 1) ? gi1 : (g == 2) ? gi2 : gi3;
            int row = ((kqv * NG + g) * 2 + chn) * 8 + ko2;
            int p = kqv * 64 + c * 8 + ko2;
            const ull* src = g_WT2 + ((size_t)gi * 256 + p) * 1024 + j0 + chn * 512 + seg * 2;
            cp16(dbase + row * 144 + seg * 16, src);
        }
        asm volatile("cp.async.commit_group;" ::: "memory");
    };

    ull acc[NG][2][2];
#pragma unroll
    for (int g = 0; g < NG; ++g) { acc[g][0][0] = 0; acc[g][0][1] = 0; acc[g][1][0] = 0; acc[g][1][1] = 0; }

    issue(0);
    for (int c = 0; c < NCHUNK; ++c) {
        if (c + 1 < NCHUNK) {
            issue(c + 1);
            asm volatile("cp.async.wait_group 1;" ::: "memory");
        } else {
            asm volatile("cp.async.wait_group 0;" ::: "memory");
        }
        __syncthreads();
        const ull* wthr = (const ull*)(smem + WS_OFF + (c & 1) * WS_BUF_BYTES)
                          + (size_t)(kq * NG * 16) * 18 + jj;
        const float* sr = sA + (rh * 2) * 512 + kq * 128 + c * 16;
#pragma unroll
        for (int it = 0; it < 8; ++it) {
            ull s0a = *(const ull*)(sr + it * 2);
            ull s0b = *(const ull*)(sr + 512 + it * 2);
            ull s1a = 0, s1b = 0;
            if (NP == 2) {
                s1a = *(const ull*)(sr + 8192 + it * 2);
                s1b = *(const ull*)(sr + 8704 + it * 2);
            }
#pragma unroll
            for (int g = 0; g < NG; ++g) {
                const int pp = (NP == 1) ? 0 : ((NG == 4) ? (g >> 1) : g);
                ull aa = (pp == 0) ? s0a : s1a;
                ull ab = (pp == 0) ? s0b : s1b;
                ull wc = wthr[(size_t)(g * 16 + it) * 18];
                ull wh = wthr[(size_t)(g * 16 + 8 + it) * 18];
                fma2(acc[g][0][0], aa, wc);
                fma2(acc[g][1][0], ab, wc);
                fma2(acc[g][0][1], aa, wh);
                fma2(acc[g][1][1], ab, wh);
            }
        }
        __syncthreads();
    }

    // reduce over kq (4) + k-parity, then epilogue
    float m0 = 0.f;
#pragma unroll
    for (int g = 0; g < NG; ++g) {
        __syncthreads();
#pragma unroll
        for (int rr = 0; rr < 2; ++rr)
#pragma unroll
            for (int ch = 0; ch < 2; ++ch)
                red[kq * 512 + ((rh * 2 + rr) * 16 + jj) * 2 + ch] = acc[g][rr][ch];
        __syncthreads();
        if (tid < 256) {
            int r = tid >> 4, jc = tid & 15, col = j0 + jc;
            float cs = 0.f, hs = 0.f;
#pragma unroll
            for (int q = 0; q < 4; ++q) {
                float2 a = unpk(red[q * 512 + (r * 16 + jc) * 2 + 0]); cs += a.x + a.y;
                float2 b = unpk(red[q * 512 + (r * 16 + jc) * 2 + 1]); hs += b.x + b.y;
            }
            if (BIAS) {
                cs += bias[(size_t)(r0 + r) * NCH + col];
                hs += bias[(size_t)(r0 + r) * NCH + 512 + col];
            }
            const int pp = (NP == 1) ? 0 : ((NG == 4) ? (g >> 1) : g);
            float sp = sA[pp * 8192 + r * 512 + col];
            int act = (g == 0) ? a0 : (g == 1) ? a1 : (g == 2) ? a2 : a3;
            float cg = 1.f / (1.f + expf(-cs));
            float hv = actf(act, hs);
            float nv = sp + cg * (hv - sp);
            float* dst = (g == 0) ? d0 : (g == 1) ? d1 : (g == 2) ? d2 : d3;
            if (dst) dst[(size_t)(r0 + r) * NHID + col] = nv;
            if (MEAN) m0 += nv;
        }
    }
    if (MEAN) {
        if (tid < 256) {
            int r = tid >> 4, col = j0 + (tid & 15);
#pragma unroll
            for (int st = 1; st <= 6; ++st)
                m0 += g_S[st][(size_t)(r0 + r) * NHID + col];
            outp[(size_t)(r0 + r) * NHID + col] = m0 * 0.125f;
        }
    }
}

__global__ void __launch_bounds__(NTHR, 1) recurrent_kernel(
    const float* __restrict__ hidden0, float* __restrict__ out, int write_tail)
{
    extern __shared__ char smem[];
    uint32_t ws_u32 = smem_u32(smem) + WS_OFF;
    const int bid = blockIdx.x;
    const int r0 = (bid >> 5) * 16;
    const int j0 = (bid & 31) * 16;

    for (int t = 0; t < T_STEPS; ++t) {
        const float* hprev = (t == 0) ? hidden0 : (out + (size_t)(t - 1) * HB);
        // P0: s0 = hprev + sig(c)*(tanh(h) - hprev); weights = W0 hidden half (gi=8), bias = X[t]
        phase<1, 1, false, true>(smem, ws_u32, hprev, nullptr, 8, 0, 0, 0, 0, 0, 0, 0,
            g_S[0], nullptr, nullptr, nullptr, g_X + (size_t)t * BATCH * NCH, nullptr, r0, j0);
        grid_bar();
        // P1: s1(tanh), s2(relu) from s0
        phase<2, 1, false, false>(smem, ws_u32, g_S[0], nullptr, 0, 1, 0, 0, 0, 1, 0, 0,
            g_S[1], g_S[2], nullptr, nullptr, nullptr, nullptr, r0, j0);
        grid_bar();
        // P2: s3(sig,s1) s4(id,s1) s5(tanh,s2) s6(relu,s2)
        phase<4, 2, false, false>(smem, ws_u32, g_S[1], g_S[2], 2, 3, 4, 5, 2, 3, 0, 1,
            g_S[3], g_S[4], g_S[5], g_S[6], nullptr, nullptr, r0, j0);
        grid_bar();
        // P3: s7(sig,s3), s8(id,s4); fused mean(s1..s8) -> out[t]
        phase<2, 2, true, false>(smem, ws_u32, g_S[3], g_S[4], 6, 7, 0, 0, 2, 3, 0, 0,
            nullptr, nullptr, nullptr, nullptr, nullptr, out + (size_t)t * HB, r0, j0);
        grid_bar();
    }
    if (write_tail) {
        const float* src = out + (size_t)(T_STEPS - 1) * HB;
        float* dstp = out + (size_t)T_STEPS * HB;
        for (int i = bid * NTHR + threadIdx.x; i < HB; i += NCTA * NTHR)
            dstp[i] = src[i];
    }
}

extern "C" void kernel_launch(void* const* d_in, const int* in_sizes, int n_in,
                              void* d_out, int out_size) {
    const float* inputs = (const float*)d_in[0];   // [512,64,512]
    const float* hidden = (const float*)d_in[1];   // [1,64,512]
    const float* W0     = (const float*)d_in[2];   // [1024,1024]
    const float* Ws     = (const float*)d_in[3];   // [8,512,1024]
    float* out = (float*)d_out;

    dim3 gw(9, 256);
    wtrans_kernel<<<gw, 256>>>(W0, Ws);

    dim3 gx(NCH / 64, (T_STEPS * BATCH) / 64);
    xprep_kernel<<<gx, 256>>>(inputs, W0);

    cudaFuncSetAttribute(recurrent_kernel,
                         cudaFuncAttributeMaxDynamicSharedMemorySize, SMEM_BYTES);
    int tail = (out_size >= T_STEPS * HB + HB) ? 1 : 0;
    recurrent_kernel<<<NCTA, NTHR, SMEM_BYTES>>>(hidden, out, tail);
}